// round 11
// baseline (speedup 1.0000x reference)
#include <cuda_runtime.h>

#define KB      16
#define NPARAMS 63
#define TPB     128
#define WSZ     32
#define S1      (32 * 33)     // phase-1 slice: 32 rows x 33 floats (params 0..31)
#define S2      (32 * 31)     // phase-2 slice: 32 rows x 31 floats (params 32..62)
#define EPSV    1e-6f

__global__ void __launch_bounds__(TPB, 7) lrs_kernel(
    const float* __restrict__ inputs,
    const float* __restrict__ params,
    float* __restrict__ out,
    int n_rows)
{
    // 4 warps x (S1 + S2) floats = 4 x 8192 B = 32768 B / block
    __shared__ float sp[(TPB / WSZ) * (S1 + S2)];

    const int wid  = threadIdx.x >> 5;
    const int lane = threadIdx.x & 31;
    const int grow0 = (blockIdx.x * (TPB / WSZ) + wid) * WSZ;  // warp's first row

    float* sl1 = sp + wid * (S1 + S2);
    float* sl2 = sl1 + S1;
    const float* gp = params + (size_t)grow0 * NPARAMS;

    // ---- Stage EVERYTHING up-front: 64 coalesced LDG bursts per lane ----
    // Phase 1: params 0..31 (w,h) -> sl1, stride 33 (conflict-free)
#pragma unroll
    for (int j = 0; j < 32; j++)
        sl1[j * 33 + lane] = gp[j * NPARAMS + lane];
    // Phase 2: params 32..62 (d, lambda) -> sl2, stride 31 (conflict-free)
    if (lane < 31) {
#pragma unroll
        for (int j = 0; j < 32; j++)
            sl2[j * 31 + lane] = gp[j * NPARAMS + 32 + lane];
    }
    __syncwarp();

    const int row = grow0 + lane;
    const float x = inputs[row];
    const float* p  = sl1 + lane * 33;   // bank (lane+k)%32
    const float* p2 = sl2 + lane * 31;   // bank (31*lane+k)%32 = (k-lane)%32

    // ---- widths softmax + knots + bin search (fused, monotone knots) ----
    float ew[KB];
    float sw = 0.f;
#pragma unroll
    for (int k = 0; k < KB; k++) { ew[k] = __expf(p[k]); sw += ew[k]; }
    const float wfac = __fdividef(1.0f - 0.001f * KB, sw);

    int   idx = 0;
    float cw  = -3.f;
    float cwn = 0.f;
    {
        float c = 0.f;
        bool psel = true;
#pragma unroll
        for (int k = 1; k <= KB; k++) {
            c += fmaf(wfac, ew[k - 1], 0.001f);
            float kn = (k == KB) ? 3.f : fmaf(6.f, c, -3.f);
            if (psel) cwn = kn;
            bool sel = (k < KB) && (kn + EPSV <= x);
            if (sel) { idx = k; cw = kn; }
            psel = sel;
        }
    }
    const float wid_w = cwn - cw;

    // ---- heights softmax + knots, select ya, yb ----
    float eh[KB];
    float sh = 0.f;
#pragma unroll
    for (int k = 0; k < KB; k++) { eh[k] = __expf(p[16 + k]); sh += eh[k]; }
    const float hfac = __fdividef(1.0f - 0.001f * KB, sh);

    float ya = -3.f, yb = 0.f;
    {
        float c = 0.f;
        float prev = -3.f;
#pragma unroll
        for (int k = 1; k <= KB; k++) {
            c += fmaf(hfac, eh[k - 1], 0.001f);
            float kn = (k == KB) ? 3.f : fmaf(6.f, c, -3.f);
            if (k - 1 == idx) { ya = prev; yb = kn; }
            prev = kn;
        }
    }

    // ---- tail params from sl2: slot k = params[32+k] ----
    //   d_lo raw = params[31+idx] -> slot idx-1 (idx>=1)
    //   d_hi raw = params[32+idx] -> slot idx   (idx<=14)
    //   lam  raw = params[47+idx] -> slot 15+idx
    const int slot_lo = (idx > 0) ? (idx - 1) : 0;
    const float dv0 = p2[slot_lo];
    const float dv1 = p2[idx];
    const float lv  = p2[15 + idx];

    const float d_lo = (idx == 0)  ? 0.999f : (__logf(1.f + __expf(dv0)) + 0.001f);
    const float d_hi = (idx == 15) ? 0.999f : (__logf(1.f + __expf(dv1)) + 0.001f);
    const float sig  = __fdividef(1.f, 1.f + __expf(-lv));
    const float lam  = fmaf(0.95f, sig, 0.025f);

    // ---- linear rational spline evaluation ----
    const float hsel   = yb - ya;
    const float dinv   = __fdividef(wid_w, hsel);        // 1/delta
    const float wb     = __fsqrt_rn(__fdividef(d_lo, d_hi));
    const float lwb    = lam * wb;
    const float wc     = (lam * d_lo + (wb - lwb) * d_hi) * dinv;
    const float l1     = 1.f - lam;
    const float yc     = __fdividef(lwb * yb + l1 * ya, l1 + lwb);
    const float theta  = __fdividef(x - cw, wid_w);
    const bool  ind    = theta <= lam;
    const float ltheta = lam - theta;
    const float wcyc   = wc * yc;
    const float wcyct  = wcyc * theta;
    const float num    = ind ? fmaf(ya, ltheta, wcyct)
                             : ((wcyc - wcyct) - wb * yb * ltheta);
    const float wcth   = wc * theta;
    const float den    = ind ? (wcth + ltheta)
                             : ((wc - wcth) - wb * ltheta);
    float outv = __fdividef(num, den);

    const float dnum = __fdividef(wc * (ind ? lam * (yc - ya)
                                            : (wb - lwb) * (yb - yc)), wid_w);
    float lad = __logf(dnum) - 2.f * __logf(fabsf(den));

    const bool outside = (x < -3.f) || (x > 3.f);
    if (outside) { outv = x; lad = 0.f; }

    out[row]          = outv;
    out[n_rows + row] = lad;
}

extern "C" void kernel_launch(void* const* d_in, const int* in_sizes, int n_in,
                              void* d_out, int out_size)
{
    const float* inputs = (const float*)d_in[0];
    const float* params = (const float*)d_in[1];
    float* out = (float*)d_out;
    const int n = in_sizes[0];            // 1048576 rows
    const int blocks = n / TPB;           // 8192
    lrs_kernel<<<blocks, TPB>>>(inputs, params, out, n);
}

// round 12
// speedup vs baseline: 1.0090x; 1.0090x over previous
#include <cuda_runtime.h>

#define KB      16
#define NPARAMS 63
#define TPB     128
#define WSZ     32
#define SLICE   (32 * 33)     // 32 rows x 33 floats (padded stride)
#define EPSV    1e-6f

__global__ void __launch_bounds__(TPB, 12) lrs_kernel(
    const float* __restrict__ inputs,
    const float* __restrict__ params,
    float* __restrict__ out,
    int n_rows)
{
    // 4 warps x (32 rows x 33 floats) = 16896 B / block
    __shared__ float sp[(TPB / WSZ) * SLICE];

    const int wid  = threadIdx.x >> 5;
    const int lane = threadIdx.x & 31;
    const int grow0 = (blockIdx.x * (TPB / WSZ) + wid) * WSZ;  // warp's first row

    float* sl = sp + wid * SLICE;
    const float* gp = params + (size_t)grow0 * NPARAMS;

    // ---- Phase 1: stage w,h (params 0..31) for this warp's 32 rows ----
#pragma unroll
    for (int j = 0; j < 32; j++)
        sl[j * 33 + lane] = gp[j * NPARAMS + lane];
    __syncwarp();

    const int row = grow0 + lane;
    const float x = inputs[row];
    float* p = sl + lane * 33;   // this lane's row; bank (lane+k)%32 -> conflict-free

    // ---- widths softmax: exp in place (slot k := exp(p[k])), no reg array ----
    float sw = 0.f;
#pragma unroll
    for (int k = 0; k < KB; k++) {
        float e = __expf(p[k]);
        p[k] = e;               // own slot, no cross-lane hazard
        sw += e;
    }
    const float wfac = __fdividef(1.0f - 0.001f * KB, sw);

    int   idx = 0;
    float cw  = -3.f;
    float cwn = 0.f;
    {
        float c = 0.f;
        bool psel = true;
#pragma unroll
        for (int k = 1; k <= KB; k++) {
            c += fmaf(wfac, p[k - 1], 0.001f);
            float kn = (k == KB) ? 3.f : fmaf(6.f, c, -3.f);
            if (psel) cwn = kn;
            bool sel = (k < KB) && (kn + EPSV <= x);
            if (sel) { idx = k; cw = kn; }
            psel = sel;
        }
    }
    const float wid_w = cwn - cw;

    // ---- heights softmax: exp in place, then knots + select ya, yb ----
    float sh = 0.f;
#pragma unroll
    for (int k = 0; k < KB; k++) {
        float e = __expf(p[16 + k]);
        p[16 + k] = e;
        sh += e;
    }
    const float hfac = __fdividef(1.0f - 0.001f * KB, sh);

    float ya = -3.f, yb = 0.f;
    {
        float c = 0.f;
        float prev = -3.f;
#pragma unroll
        for (int k = 1; k <= KB; k++) {
            c += fmaf(hfac, p[15 + k], 0.001f);
            float kn = (k == KB) ? 3.f : fmaf(6.f, c, -3.f);
            if (k - 1 == idx) { ya = prev; yb = kn; }
            prev = kn;
        }
    }

    // ---- Phase 2: reuse the same slice for params 32..62 (d, lambda) ----
    __syncwarp();                         // all lanes done reading w,h slots
    if (lane < 31) {
#pragma unroll
        for (int j = 0; j < 32; j++)
            sl[j * 33 + lane] = gp[j * NPARAMS + 32 + lane];
    }
    __syncwarp();

    // slot k holds param[32+k]:
    //   d_lo raw = params[31+idx] -> slot idx-1 (idx>=1)
    //   d_hi raw = params[32+idx] -> slot idx   (idx<=14)
    //   lam  raw = params[47+idx] -> slot 15+idx
    const int slot_lo = (idx > 0) ? (idx - 1) : 0;
    const float dv0 = p[slot_lo];
    const float dv1 = p[idx];
    const float lv  = p[15 + idx];

    const float d_lo = (idx == 0)  ? 0.999f : (__logf(1.f + __expf(dv0)) + 0.001f);
    const float d_hi = (idx == 15) ? 0.999f : (__logf(1.f + __expf(dv1)) + 0.001f);
    const float sig  = __fdividef(1.f, 1.f + __expf(-lv));
    const float lam  = fmaf(0.95f, sig, 0.025f);

    // ---- linear rational spline evaluation ----
    const float hsel   = yb - ya;
    const float dinv   = __fdividef(wid_w, hsel);        // 1/delta
    const float wb     = __fsqrt_rn(__fdividef(d_lo, d_hi));
    const float lwb    = lam * wb;
    const float wc     = (lam * d_lo + (wb - lwb) * d_hi) * dinv;
    const float l1     = 1.f - lam;
    const float yc     = __fdividef(lwb * yb + l1 * ya, l1 + lwb);
    const float theta  = __fdividef(x - cw, wid_w);
    const bool  ind    = theta <= lam;
    const float ltheta = lam - theta;
    const float wcyc   = wc * yc;
    const float wcyct  = wcyc * theta;
    const float num    = ind ? fmaf(ya, ltheta, wcyct)
                             : ((wcyc - wcyct) - wb * yb * ltheta);
    const float wcth   = wc * theta;
    const float den    = ind ? (wcth + ltheta)
                             : ((wc - wcth) - wb * ltheta);
    float outv = __fdividef(num, den);

    const float dnum = __fdividef(wc * (ind ? lam * (yc - ya)
                                            : (wb - lwb) * (yb - yc)), wid_w);
    float lad = __logf(dnum) - 2.f * __logf(fabsf(den));

    const bool outside = (x < -3.f) || (x > 3.f);
    if (outside) { outv = x; lad = 0.f; }

    out[row]          = outv;
    out[n_rows + row] = lad;
}

extern "C" void kernel_launch(void* const* d_in, const int* in_sizes, int n_in,
                              void* d_out, int out_size)
{
    const float* inputs = (const float*)d_in[0];
    const float* params = (const float*)d_in[1];
    float* out = (float*)d_out;
    const int n = in_sizes[0];            // 1048576 rows
    const int blocks = n / TPB;           // 8192
    lrs_kernel<<<blocks, TPB>>>(inputs, params, out, n);
}